// round 1
// baseline (speedup 1.0000x reference)
#include <cuda_runtime.h>
#include <cstddef>

// Problem constants
#define BB 16
#define CC 256
#define HH 32
#define WW 32
#define KK 81
#define PADR 4
#define NPIX (HH*WW)            // 1024
#define FLT_ELEMS (BB*CC*NPIX)  // 4194304

// ---------------- device scratch (no allocation allowed) ----------------
__device__ __align__(16) float g_mr[BB*KK*NPIX];     // mapped residuals  [b,k,y,x]
__device__ __align__(16) float g_wm[BB*KK*NPIX];     // w * score_mask    [b,k,y,x]
__device__ __align__(16) float g_fgrad[FLT_ELEMS];   // filter gradient
__device__ float g_alpha_num[BB*NPIX];
__device__ float g_alpha_den[BB*NPIX];
__device__ float g_label[KK];
__device__ float g_m[KK];
__device__ float g_w[KK];
__device__ float g_params[2];      // [0]=step_length, [1]=reg_weight
__device__ float g_lr2[3];         // sum loss_residuals^2 per iter
__device__ float g_flt2[3];        // sum flt^2 per iter

// ---------------- precompute: distance-map projections ----------------
__global__ void k_pre(const float* __restrict__ label_w,
                      const float* __restrict__ mask_w,
                      const float* __restrict__ spatial_w,
                      const float* __restrict__ lsl,
                      const float* __restrict__ freg) {
    int k = threadIdx.x;
    if (k == 0) {
        g_params[0] = expf(lsl[0]);
        float r2 = freg[0] * freg[0];
        r2 = fmaxf(r2, 1e-10f);                 // clip at MIN_FILTER_REG^2
        g_params[1] = r2 / (256.0f * 256.0f);   // / feat_dim^2
        for (int i = 0; i < 3; ++i) { g_lr2[i] = 0.f; g_flt2[i] = 0.f; }
    }
    if (k < KK) {
        int i = k / 9, j = k % 9;
        float di = (float)(i - PADR), dj = (float)(j - PADR);
        float dist = sqrtf(di * di + dj * dj);
        float lab = 0.f, ml = 0.f, sw = 0.f;
        #pragma unroll
        for (int d = 0; d < 10; ++d) {
            float bd = dist * 2.0f - (float)d;   // dist / 0.5 - d
            float bv;
            if (d < 9) bv = fmaxf(1.0f - fabsf(bd), 0.0f);
            else       bv = fminf(fmaxf(1.0f + bd, 0.0f), 1.0f);
            lab += bv * label_w[d];
            ml  += bv * mask_w[d];
            sw  += bv * spatial_w[d];
        }
        g_label[k] = lab;
        g_m[k]     = 1.0f / (1.0f + expf(-ml));
        g_w[k]     = sw;
    }
}

// ---------------- zero per-iteration accumulators ----------------
__global__ void k_zero() {
    int idx = blockIdx.x * blockDim.x + threadIdx.x;
    if (idx < BB * NPIX) { g_alpha_num[idx] = 0.f; g_alpha_den[idx] = 0.f; }
}

__device__ __forceinline__ float block_sum_128(float v, float* s_red, int tid) {
    s_red[tid] = v;
    __syncthreads();
    #pragma unroll
    for (int o = 64; o > 0; o >>= 1) {
        if (tid < o) s_red[tid] += s_red[tid + o];
        __syncthreads();
    }
    return s_red[0];
}

// ---------------- correlation kernel (used for scores and scores_grad) ----------------
// Grid: (4 ytiles, 3 dy-groups, 16 batch). Block: 128 threads = 8 rows x 16 pixel-pairs.
// Each thread owns 2 adjacent x pixels, accumulates 27 k-channels (3 dy x 9 dx).
// IS_A=true : src = filter; writes mr/wm, accumulates loss sum.
// IS_A=false: src = g_fgrad; reads wm, accumulates alpha_den per pixel.
template <bool IS_A>
__global__ __launch_bounds__(128)
void k_corr(const float* __restrict__ srcp, const float* __restrict__ feat, int iter) {
    __shared__ __align__(16) float s_feat[8][10][40];
    __shared__ __align__(16) float s_flt[8][8][32];
    __shared__ float s_lab[27], s_m[27], s_w[27];
    __shared__ float s_red[128];

    const int tid = threadIdx.x;
    const int ty = tid >> 4;          // 0..7 (row in tile)
    const int txq = tid & 15;         // 0..15 (pixel pair)
    const int b  = blockIdx.z;
    const int y0 = blockIdx.x * 8;
    const int d0 = blockIdx.y * 3;    // dy group start
    const int y  = y0 + ty;
    const int x0 = 2 * txq;

    const float* src = IS_A ? srcp : g_fgrad;

    if (tid < 27) {
        int kg = d0 * 9 + tid;
        s_lab[tid] = g_label[kg];
        s_m[tid]   = g_m[kg];
        s_w[tid]   = g_w[kg];
    }

    float accA[27], accB[27];
    #pragma unroll
    for (int i = 0; i < 27; ++i) { accA[i] = 0.f; accB[i] = 0.f; }

    for (int cc = 0; cc < 32; ++cc) {
        __syncthreads();
        const float* featb = feat + ((size_t)(b * CC + cc * 8)) * NPIX;
        for (int i = tid; i < 8 * 10 * 40; i += 128) {
            int c = i / 400; int rem = i % 400;
            int r = rem / 40; int col = rem % 40;
            int grow = y0 + d0 - 4 + r;
            int gcol = col - 4;
            float v = 0.f;
            if ((unsigned)grow < 32u && (unsigned)gcol < 32u)
                v = featb[c * NPIX + grow * WW + gcol];
            s_feat[c][r][col] = v;
        }
        const float* srcb = src + ((size_t)(b * CC + cc * 8)) * NPIX;
        for (int i = tid; i < 8 * 8 * 32; i += 128) {
            int c = i / 256; int p = i % 256;
            s_flt[c][p >> 5][p & 31] = srcb[c * NPIX + (y0 + (p >> 5)) * WW + (p & 31)];
        }
        __syncthreads();

        #pragma unroll
        for (int c = 0; c < 8; ++c) {
            float2 fv = *(const float2*)&s_flt[c][ty][x0];
            #pragma unroll
            for (int dy2 = 0; dy2 < 3; ++dy2) {
                const float* fr = &s_feat[c][ty + dy2][x0];
                float f[10];
                #pragma unroll
                for (int q = 0; q < 5; ++q) {
                    float2 t = *(const float2*)&fr[2 * q];
                    f[2 * q] = t.x; f[2 * q + 1] = t.y;
                }
                #pragma unroll
                for (int dx = 0; dx < 9; ++dx) {
                    accA[dy2 * 9 + dx] = fmaf(fv.x, f[dx],     accA[dy2 * 9 + dx]);
                    accB[dy2 * 9 + dx] = fmaf(fv.y, f[dx + 1], accB[dy2 * 9 + dx]);
                }
            }
        }
    }

    if (IS_A) {
        float lsum = 0.f;
        #pragma unroll
        for (int kk = 0; kk < 27; ++kk) {
            int kg = d0 * 9 + kk;
            float m = s_m[kk], w = s_w[kk], lab = s_lab[kk];
            float cm = 0.5f * (1.0f - m), cp = 0.5f * (1.0f + m);

            float sA = accA[kk];
            float sgnA = (sA > 0.f) ? 1.0f : ((sA < 0.f) ? -1.0f : 0.0f);
            float sactA = cm * fabsf(sA) + cp * sA;
            float smaskA = cm * sgnA + cp;
            float lrA = w * (sactA - lab);
            float mrA = smaskA * w * lrA;
            float wmA = w * smaskA;

            float sB = accB[kk];
            float sgnB = (sB > 0.f) ? 1.0f : ((sB < 0.f) ? -1.0f : 0.0f);
            float sactB = cm * fabsf(sB) + cp * sB;
            float smaskB = cm * sgnB + cp;
            float lrB = w * (sactB - lab);
            float mrB = smaskB * w * lrB;
            float wmB = w * smaskB;

            size_t base = (((size_t)b * KK + kg) * HH + y) * WW + x0;
            *(float2*)&g_mr[base] = make_float2(mrA, mrB);
            *(float2*)&g_wm[base] = make_float2(wmA, wmB);
            lsum += lrA * lrA + lrB * lrB;
        }
        __syncthreads();
        float tot = block_sum_128(lsum, s_red, tid);
        if (tid == 0) atomicAdd(&g_lr2[iter], tot);
    } else {
        float denA = 0.f, denB = 0.f;
        #pragma unroll
        for (int kk = 0; kk < 27; ++kk) {
            int kg = d0 * 9 + kk;
            size_t base = (((size_t)b * KK + kg) * HH + y) * WW + x0;
            float2 wm2 = *(const float2*)&g_wm[base];
            float sgA = wm2.x * accA[kk];
            float sgB = wm2.y * accB[kk];
            denA += sgA * sgA;
            denB += sgB * sgB;
        }
        int p = (b << 10) + (y << 5) + x0;
        atomicAdd(&g_alpha_den[p], denA);
        atomicAdd(&g_alpha_den[p + 1], denB);
    }
}

// ---------------- transpose correlation: filter_grad ----------------
// Grid: (8 ytiles, 2 channel-splits, 16 batch). Block: 128 = 4 rows x 32 cols.
// Each thread owns one pixel; loads its 81 mapped residuals into registers,
// then loops over 128 channels producing filter_grad; accumulates alpha_num, flt^2.
__global__ __launch_bounds__(128)
void k_btrans(const float* __restrict__ flt, const float* __restrict__ feat, int iter) {
    __shared__ __align__(16) float s_feat[8][12][40];
    __shared__ float s_red[128];

    const int tid = threadIdx.x;
    const int tx = tid & 31;
    const int ty = tid >> 5;          // 0..3
    const int b  = blockIdx.z;
    const int cs = blockIdx.y;        // 0..1
    const int y0 = blockIdx.x * 4;
    const int y  = y0 + ty;
    const int x  = tx;

    const float rw = g_params[1];

    float mrv[KK];
    #pragma unroll
    for (int k = 0; k < KK; ++k)
        mrv[k] = g_mr[(((size_t)b * KK + k) * HH + y) * WW + x];

    float anum = 0.f, fl2 = 0.f;

    for (int cc = 0; cc < 16; ++cc) {
        int cbase = cs * 128 + cc * 8;
        __syncthreads();
        const float* featb = feat + ((size_t)(b * CC + cbase)) * NPIX;
        for (int i = tid; i < 8 * 12 * 40; i += 128) {
            int c = i / 480; int rem = i % 480;
            int r = rem / 40; int col = rem % 40;
            int grow = y0 - 4 + r;
            int gcol = col - 4;
            float v = 0.f;
            if ((unsigned)grow < 32u && (unsigned)gcol < 32u)
                v = featb[c * NPIX + grow * WW + gcol];
            s_feat[c][r][col] = v;
        }
        __syncthreads();

        #pragma unroll
        for (int c = 0; c < 8; ++c) {
            float g = 0.f;
            #pragma unroll
            for (int dy = 0; dy < 9; ++dy) {
                const float* fr = &s_feat[c][ty + dy][tx];
                #pragma unroll
                for (int dx = 0; dx < 9; ++dx)
                    g = fmaf(mrv[dy * 9 + dx], fr[dx], g);
            }
            size_t gidx = (((size_t)(b * CC + cbase + c)) << 10) + (y << 5) + x;
            float fl = flt[gidx];
            g = fmaf(rw, fl, g);
            g_fgrad[gidx] = g;
            anum += g * g;
            fl2 += fl * fl;
        }
    }

    atomicAdd(&g_alpha_num[(b << 10) + (y << 5) + x], anum);
    __syncthreads();
    float tot = block_sum_128(fl2, s_red, tid);
    if (tid == 0) atomicAdd(&g_flt2[iter], tot);
}

// ---------------- filter update ----------------
__global__ void k_update(float* __restrict__ flt) {
    int idx = blockIdx.x * 256 + threadIdx.x;
    float step = g_params[0], rw = g_params[1];
    int spix = idx & 1023;
    int b = idx >> 18;                 // / (256*1024)
    int p = (b << 10) + spix;
    float num = g_alpha_num[p];
    float den = g_alpha_den[p] + rw * num;
    den = fmaxf(den, 1e-8f);
    float alpha = num / den;
    flt[idx] -= step * alpha * g_fgrad[idx];
}

// ---------------- final scalars ----------------
__global__ void k_fin(float* __restrict__ out) {
    int i = threadIdx.x;
    if (i < 3) {
        float rw = g_params[1];
        float src = 0.5f * g_lr2[i] / (float)BB;
        float reg = 0.5f * rw * g_flt2[i] / (float)BB;
        out[FLT_ELEMS + i]     = src + reg;   // tr
        out[FLT_ELEMS + 3 + i] = src;         // tr_src
        out[FLT_ELEMS + 6 + i] = reg;         // tr_reg
    }
}

// ---------------- launch ----------------
extern "C" void kernel_launch(void* const* d_in, const int* in_sizes, int n_in,
                              void* d_out, int out_size) {
    const float* flt_in = (const float*)d_in[0];
    const float* feat   = (const float*)d_in[1];
    const float* lw     = (const float*)d_in[2];
    const float* mw     = (const float*)d_in[3];
    const float* sw     = (const float*)d_in[4];
    const float* lsl    = (const float*)d_in[5];
    const float* fr     = (const float*)d_in[6];
    float* out = (float*)d_out;

    size_t ncpy = (out_size < FLT_ELEMS) ? (size_t)out_size : (size_t)FLT_ELEMS;
    cudaMemcpyAsync(out, flt_in, ncpy * sizeof(float), cudaMemcpyDeviceToDevice);

    k_pre<<<1, 128>>>(lw, mw, sw, lsl, fr);

    for (int it = 0; it < 3; ++it) {
        k_zero<<<64, 256>>>();
        k_corr<true><<<dim3(4, 3, BB), 128>>>(out, feat, it);
        k_btrans<<<dim3(8, 2, BB), 128>>>(out, feat, it);
        k_corr<false><<<dim3(4, 3, BB), 128>>>(nullptr, feat, it);
        k_update<<<FLT_ELEMS / 256, 256>>>(out);
    }

    if (out_size >= FLT_ELEMS + 9)
        k_fin<<<1, 32>>>(out);
}

// round 6
// speedup vs baseline: 1.7450x; 1.7450x over previous
#include <cuda_runtime.h>
#include <cstddef>

// Problem constants
#define BB 16
#define CC 256
#define HH 32
#define WW 32
#define KK 81
#define PADR 4
#define NPIX (HH*WW)            // 1024
#define FLT_ELEMS (BB*CC*NPIX)  // 4194304
#define NSLICE 4                // channel splits in corr

// ---------------- device scratch (no allocation allowed) ----------------
__device__ __align__(16) float g_part[NSLICE*BB*KK*NPIX]; // corr partial sums
__device__ __align__(16) float g_mr[BB*KK*NPIX];     // mapped residuals  [b,k,p]
__device__ __align__(16) float g_wm[BB*KK*NPIX];     // w * score_mask    [b,k,p]
__device__ __align__(16) float g_fgrad[FLT_ELEMS];   // filter gradient
__device__ float g_alpha_num[BB*NPIX];
__device__ float g_alpha_den[BB*NPIX];
__device__ float g_label[KK];
__device__ float g_m[KK];
__device__ float g_w[KK];
__device__ float g_params[2];      // [0]=step_length, [1]=reg_weight
__device__ float g_lr2[3];         // sum loss_residuals^2 per iter
__device__ float g_flt2[3];        // sum flt^2 per iter

// ---------------- precompute: distance-map projections ----------------
__global__ void k_pre(const float* __restrict__ label_w,
                      const float* __restrict__ mask_w,
                      const float* __restrict__ spatial_w,
                      const float* __restrict__ lsl,
                      const float* __restrict__ freg) {
    int k = threadIdx.x;
    if (k == 0) {
        g_params[0] = expf(lsl[0]);
        float r2 = freg[0] * freg[0];
        r2 = fmaxf(r2, 1e-10f);                 // clip at MIN_FILTER_REG^2
        g_params[1] = r2 / (256.0f * 256.0f);   // / feat_dim^2
        for (int i = 0; i < 3; ++i) { g_lr2[i] = 0.f; g_flt2[i] = 0.f; }
    }
    if (k < KK) {
        int i = k / 9, j = k % 9;
        float di = (float)(i - PADR), dj = (float)(j - PADR);
        float dist = sqrtf(di * di + dj * dj);
        float lab = 0.f, ml = 0.f, sw = 0.f;
        #pragma unroll
        for (int d = 0; d < 10; ++d) {
            float bd = dist * 2.0f - (float)d;   // dist / 0.5 - d
            float bv;
            if (d < 9) bv = fmaxf(1.0f - fabsf(bd), 0.0f);
            else       bv = fminf(fmaxf(1.0f + bd, 0.0f), 1.0f);
            lab += bv * label_w[d];
            ml  += bv * mask_w[d];
            sw  += bv * spatial_w[d];
        }
        g_label[k] = lab;
        g_m[k]     = 1.0f / (1.0f + expf(-ml));
        g_w[k]     = sw;
    }
}

// ---------------- zero per-iteration accumulators ----------------
__global__ void k_zero() {
    int idx = blockIdx.x * blockDim.x + threadIdx.x;
    if (idx < BB * NPIX) { g_alpha_num[idx] = 0.f; g_alpha_den[idx] = 0.f; }
}

// ---------------- correlation partial kernel ----------------
// Grid: (12 = 4 ytiles * 3 dy-groups, 4 channel-slices, 16 batch). Block: 128.
// 8 rows x 16 pixel-pairs; each thread owns 2 adjacent x pixels, 27 k-channels.
// Reduces 64 channels; partial sum -> g_part[slice].
// srcp == nullptr means "use g_fgrad".
__global__ __launch_bounds__(128)
void k_corrP(const float* __restrict__ srcp, const float* __restrict__ feat) {
    __shared__ __align__(16) float s_feat[8][10][40];
    __shared__ __align__(16) float s_flt[8][8][32];

    const int tid = threadIdx.x;
    const int ty = tid >> 4;          // 0..7
    const int txq = tid & 15;         // 0..15
    const int bx = blockIdx.x;
    const int ytile = bx / 3;
    const int d0 = (bx % 3) * 3;      // dy group start
    const int slice = blockIdx.y;     // 0..3
    const int b  = blockIdx.z;
    const int y0 = ytile * 8;
    const int y  = y0 + ty;
    const int x0 = 2 * txq;
    const int cbase = slice * 64;

    const float* src = srcp ? srcp : g_fgrad;

    float accA[27], accB[27];
    #pragma unroll
    for (int i = 0; i < 27; ++i) { accA[i] = 0.f; accB[i] = 0.f; }

    for (int cc = 0; cc < 8; ++cc) {
        __syncthreads();
        const float* featb = feat + ((size_t)(b * CC + cbase + cc * 8)) * NPIX;
        for (int i = tid; i < 8 * 10 * 40; i += 128) {
            int c = i / 400; int rem = i % 400;
            int r = rem / 40; int col = rem % 40;
            int grow = y0 + d0 - 4 + r;
            int gcol = col - 4;
            float v = 0.f;
            if ((unsigned)grow < 32u && (unsigned)gcol < 32u)
                v = featb[c * NPIX + grow * WW + gcol];
            s_feat[c][r][col] = v;
        }
        const float* srcb = src + ((size_t)(b * CC + cbase + cc * 8)) * NPIX;
        for (int i = tid; i < 8 * 8 * 32; i += 128) {
            int c = i / 256; int p = i % 256;
            s_flt[c][p >> 5][p & 31] = srcb[c * NPIX + (y0 + (p >> 5)) * WW + (p & 31)];
        }
        __syncthreads();

        #pragma unroll
        for (int c = 0; c < 8; ++c) {
            float2 fv = *(const float2*)&s_flt[c][ty][x0];
            #pragma unroll
            for (int dy2 = 0; dy2 < 3; ++dy2) {
                const float* fr = &s_feat[c][ty + dy2][x0];
                float f[10];
                #pragma unroll
                for (int q = 0; q < 5; ++q) {
                    float2 t = *(const float2*)&fr[2 * q];
                    f[2 * q] = t.x; f[2 * q + 1] = t.y;
                }
                #pragma unroll
                for (int dx = 0; dx < 9; ++dx) {
                    accA[dy2 * 9 + dx] = fmaf(fv.x, f[dx],     accA[dy2 * 9 + dx]);
                    accB[dy2 * 9 + dx] = fmaf(fv.y, f[dx + 1], accB[dy2 * 9 + dx]);
                }
            }
        }
    }

    #pragma unroll
    for (int kk = 0; kk < 27; ++kk) {
        int kg = d0 * 9 + kk;
        size_t base = (((size_t)(slice * BB + b) * KK + kg) << 10) + (y << 5) + x0;
        *(float2*)&g_part[base] = make_float2(accA[kk], accB[kk]);
    }
}

// ---------------- combine A: activation, residuals, loss ----------------
__global__ __launch_bounds__(256)
void k_postA(int iter) {
    __shared__ float s_red[256];
    int idx = blockIdx.x * 256 + threadIdx.x;   // < 16*81*1024
    int p = idx & 1023;
    int t = idx >> 10;
    int b = t / KK;
    int k = t - b * KK;

    float s = 0.f;
    #pragma unroll
    for (int sl = 0; sl < NSLICE; ++sl)
        s += g_part[(((size_t)(sl * BB + b) * KK + k) << 10) + p];

    float m = g_m[k], w = g_w[k], lab = g_label[k];
    float cm = 0.5f * (1.0f - m), cp = 0.5f * (1.0f + m);
    float sgn = (s > 0.f) ? 1.0f : ((s < 0.f) ? -1.0f : 0.0f);
    float sact = cm * fabsf(s) + cp * s;
    float smask = cm * sgn + cp;
    float lr = w * (sact - lab);
    size_t base = (((size_t)b * KK + k) << 10) + p;
    g_mr[base] = smask * w * lr;
    g_wm[base] = w * smask;

    // block reduce lr^2
    int tid = threadIdx.x;
    s_red[tid] = lr * lr;
    __syncthreads();
    #pragma unroll
    for (int o = 128; o > 0; o >>= 1) {
        if (tid < o) s_red[tid] += s_red[tid + o];
        __syncthreads();
    }
    if (tid == 0) atomicAdd(&g_lr2[iter], s_red[0]);
}

// ---------------- combine B: scores_grad -> alpha_den ----------------
__global__ __launch_bounds__(256)
void k_postB() {
    int idx = blockIdx.x * 256 + threadIdx.x;
    int p = idx & 1023;
    int t = idx >> 10;
    int b = t / KK;
    int k = t - b * KK;

    float s = 0.f;
    #pragma unroll
    for (int sl = 0; sl < NSLICE; ++sl)
        s += g_part[(((size_t)(sl * BB + b) * KK + k) << 10) + p];

    float wm = g_wm[(((size_t)b * KK + k) << 10) + p];
    float sg = wm * s;
    atomicAdd(&g_alpha_den[(b << 10) + p], sg * sg);
}

// ---------------- transpose correlation: filter_grad ----------------
// Grid: (8 ytiles, 8 channel-splits, 16 batch). Block: 128 = 4 rows x 32 cols.
// Each thread owns one pixel with all 81 residuals in registers; 32 channels.
__global__ __launch_bounds__(128)
void k_btrans(const float* __restrict__ flt, const float* __restrict__ feat, int iter) {
    __shared__ __align__(16) float s_feat[8][12][40];
    __shared__ float s_red[128];

    const int tid = threadIdx.x;
    const int tx = tid & 31;
    const int ty = tid >> 5;          // 0..3
    const int b  = blockIdx.z;
    const int cs = blockIdx.y;        // 0..7
    const int y0 = blockIdx.x * 4;
    const int y  = y0 + ty;
    const int x  = tx;

    const float rw = g_params[1];

    float mrv[KK];
    #pragma unroll
    for (int k = 0; k < KK; ++k)
        mrv[k] = g_mr[(((size_t)b * KK + k) << 10) + (y << 5) + x];

    float anum = 0.f, fl2 = 0.f;

    for (int cc = 0; cc < 4; ++cc) {
        int cbase = cs * 32 + cc * 8;
        __syncthreads();
        const float* featb = feat + ((size_t)(b * CC + cbase)) * NPIX;
        for (int i = tid; i < 8 * 12 * 40; i += 128) {
            int c = i / 480; int rem = i % 480;
            int r = rem / 40; int col = rem % 40;
            int grow = y0 - 4 + r;
            int gcol = col - 4;
            float v = 0.f;
            if ((unsigned)grow < 32u && (unsigned)gcol < 32u)
                v = featb[c * NPIX + grow * WW + gcol];
            s_feat[c][r][col] = v;
        }
        __syncthreads();

        #pragma unroll
        for (int c = 0; c < 8; ++c) {
            float g = 0.f;
            #pragma unroll
            for (int dy = 0; dy < 9; ++dy) {
                const float* fr = &s_feat[c][ty + dy][tx];
                #pragma unroll
                for (int dx = 0; dx < 9; ++dx)
                    g = fmaf(mrv[dy * 9 + dx], fr[dx], g);
            }
            size_t gidx = (((size_t)(b * CC + cbase + c)) << 10) + (y << 5) + x;
            float fl = flt[gidx];
            g = fmaf(rw, fl, g);
            g_fgrad[gidx] = g;
            anum += g * g;
            fl2 += fl * fl;
        }
    }

    atomicAdd(&g_alpha_num[(b << 10) + (y << 5) + x], anum);
    s_red[tid] = fl2;
    __syncthreads();
    #pragma unroll
    for (int o = 64; o > 0; o >>= 1) {
        if (tid < o) s_red[tid] += s_red[tid + o];
        __syncthreads();
    }
    if (tid == 0) atomicAdd(&g_flt2[iter], s_red[0]);
}

// ---------------- filter update ----------------
__global__ void k_update(float* __restrict__ flt) {
    int idx = blockIdx.x * 256 + threadIdx.x;
    float step = g_params[0], rw = g_params[1];
    int spix = idx & 1023;
    int b = idx >> 18;                 // / (256*1024)
    int p = (b << 10) + spix;
    float num = g_alpha_num[p];
    float den = g_alpha_den[p] + rw * num;
    den = fmaxf(den, 1e-8f);
    float alpha = num / den;
    flt[idx] -= step * alpha * g_fgrad[idx];
}

// ---------------- final scalars ----------------
__global__ void k_fin(float* __restrict__ out) {
    int i = threadIdx.x;
    if (i < 3) {
        float rw = g_params[1];
        float src = 0.5f * g_lr2[i] / (float)BB;
        float reg = 0.5f * rw * g_flt2[i] / (float)BB;
        out[FLT_ELEMS + i]     = src + reg;   // tr
        out[FLT_ELEMS + 3 + i] = src;         // tr_src
        out[FLT_ELEMS + 6 + i] = reg;         // tr_reg
    }
}

// ---------------- launch ----------------
extern "C" void kernel_launch(void* const* d_in, const int* in_sizes, int n_in,
                              void* d_out, int out_size) {
    const float* flt_in = (const float*)d_in[0];
    const float* feat   = (const float*)d_in[1];
    const float* lw     = (const float*)d_in[2];
    const float* mw     = (const float*)d_in[3];
    const float* sw     = (const float*)d_in[4];
    const float* lsl    = (const float*)d_in[5];
    const float* fr     = (const float*)d_in[6];
    float* out = (float*)d_out;

    size_t ncpy = (out_size < FLT_ELEMS) ? (size_t)out_size : (size_t)FLT_ELEMS;
    cudaMemcpyAsync(out, flt_in, ncpy * sizeof(float), cudaMemcpyDeviceToDevice);

    k_pre<<<1, 128>>>(lw, mw, sw, lsl, fr);

    const int POST_BLOCKS = (BB * KK * NPIX) / 256;   // 5184

    for (int it = 0; it < 3; ++it) {
        k_zero<<<64, 256>>>();
        k_corrP<<<dim3(12, NSLICE, BB), 128>>>(out, feat);
        k_postA<<<POST_BLOCKS, 256>>>(it);
        k_btrans<<<dim3(8, 8, BB), 128>>>(out, feat, it);
        k_corrP<<<dim3(12, NSLICE, BB), 128>>>(nullptr, feat);
        k_postB<<<POST_BLOCKS, 256>>>();
        k_update<<<FLT_ELEMS / 256, 256>>>(out);
    }

    if (out_size >= FLT_ELEMS + 9)
        k_fin<<<1, 32>>>(out);
}

// round 9
// speedup vs baseline: 3.0677x; 1.7580x over previous
#include <cuda_runtime.h>
#include <cstddef>
#include <cstdint>

// Problem constants
#define BB 16
#define CC 256
#define HH 32
#define WW 32
#define KK 81
#define PADR 4
#define NPIX (HH*WW)            // 1024
#define FLT_ELEMS (BB*CC*NPIX)  // 4194304
#define NSLICE 4                // channel splits in corr

// ---------------- cp.async helpers ----------------
__device__ __forceinline__ uint32_t smem_u32(const void* p) {
    return (uint32_t)__cvta_generic_to_shared(p);
}
#define CP_ASYNC16(dst_u32, src_ptr) \
    asm volatile("cp.async.cg.shared.global [%0], [%1], 16;" :: "r"(dst_u32), "l"(src_ptr) : "memory")
#define CP_COMMIT() asm volatile("cp.async.commit_group;" ::: "memory")
template <int N>
__device__ __forceinline__ void cp_wait() {
    asm volatile("cp.async.wait_group %0;" :: "n"(N) : "memory");
}

// ---------------- device scratch (no allocation allowed) ----------------
__device__ __align__(16) float g_part[NSLICE*BB*KK*NPIX]; // corr partial sums
__device__ __align__(16) float g_mr[BB*KK*NPIX];     // mapped residuals  [b,k,p]
__device__ __align__(16) float g_wm[BB*KK*NPIX];     // w * score_mask    [b,k,p]
__device__ __align__(16) float g_fgrad[FLT_ELEMS];   // filter gradient
__device__ float g_alpha_num[BB*NPIX];
__device__ float g_alpha_den[BB*NPIX];
__device__ float g_label[KK];
__device__ float g_m[KK];
__device__ float g_w[KK];
__device__ float g_params[2];      // [0]=step_length, [1]=reg_weight
__device__ float g_lr2[3];         // sum loss_residuals^2 per iter
__device__ float g_flt2[3];        // sum flt^2 per iter

// ---------------- precompute: distance-map projections ----------------
__global__ void k_pre(const float* __restrict__ label_w,
                      const float* __restrict__ mask_w,
                      const float* __restrict__ spatial_w,
                      const float* __restrict__ lsl,
                      const float* __restrict__ freg) {
    int k = threadIdx.x;
    if (k == 0) {
        g_params[0] = expf(lsl[0]);
        float r2 = freg[0] * freg[0];
        r2 = fmaxf(r2, 1e-10f);                 // clip at MIN_FILTER_REG^2
        g_params[1] = r2 / (256.0f * 256.0f);   // / feat_dim^2
        for (int i = 0; i < 3; ++i) { g_lr2[i] = 0.f; g_flt2[i] = 0.f; }
    }
    if (k < KK) {
        int i = k / 9, j = k % 9;
        float di = (float)(i - PADR), dj = (float)(j - PADR);
        float dist = sqrtf(di * di + dj * dj);
        float lab = 0.f, ml = 0.f, sw = 0.f;
        #pragma unroll
        for (int d = 0; d < 10; ++d) {
            float bd = dist * 2.0f - (float)d;   // dist / 0.5 - d
            float bv;
            if (d < 9) bv = fmaxf(1.0f - fabsf(bd), 0.0f);
            else       bv = fminf(fmaxf(1.0f + bd, 0.0f), 1.0f);
            lab += bv * label_w[d];
            ml  += bv * mask_w[d];
            sw  += bv * spatial_w[d];
        }
        g_label[k] = lab;
        g_m[k]     = 1.0f / (1.0f + expf(-ml));
        g_w[k]     = sw;
    }
}

// ---------------- zero per-iteration accumulators ----------------
__global__ void k_zero() {
    int idx = blockIdx.x * blockDim.x + threadIdx.x;
    if (idx < BB * NPIX) { g_alpha_num[idx] = 0.f; g_alpha_den[idx] = 0.f; }
}

// ---------------- correlation partial kernel ----------------
// Grid: (12 = 4 ytiles * 3 dy-groups, 4 channel-slices, 16 batch). Block: 128.
// 8 rows x 16 pixel-pairs; each thread owns 2 adjacent x pixels, 27 k-channels.
// feat staged through double-buffered smem via cp.async; flt read directly (no reuse).
// Reduces 64 channels; partial sum -> g_part[slice]. srcp==nullptr -> g_fgrad.
__global__ __launch_bounds__(128)
void k_corrP(const float* __restrict__ srcp, const float* __restrict__ feat) {
    __shared__ __align__(16) float s_feat[2][8][10][40];

    const int tid = threadIdx.x;
    const int ty = tid >> 4;          // 0..7
    const int txq = tid & 15;         // 0..15
    const int bx = blockIdx.x;
    const int ytile = bx / 3;
    const int d0 = (bx % 3) * 3;      // dy group start
    const int slice = blockIdx.y;     // 0..3
    const int b  = blockIdx.z;
    const int y0 = ytile * 8;
    const int y  = y0 + ty;
    const int x0 = 2 * txq;
    const int cbase = slice * 64;

    const float* src = srcp ? srcp : g_fgrad;

    // pre-zero both buffers (halo cells stay zero through all chunks)
    {
        float* sf = &s_feat[0][0][0][0];
        for (int i = tid; i < 2 * 8 * 10 * 40; i += 128) sf[i] = 0.f;
    }
    __syncthreads();

    // prefetch lambda: chunk cc -> buffer buf (valid interior cells only)
    auto prefetch = [&](int cc, int buf) {
        const float* featb = feat + ((size_t)(b * CC + cbase + cc * 8)) * NPIX;
        #pragma unroll
        for (int j = 0; j < 5; ++j) {
            int i = tid + j * 128;        // 0..639
            int c = i / 80; int rem = i % 80;
            int r = rem >> 3; int q = rem & 7;
            int grow = y0 + d0 - 4 + r;
            if ((unsigned)grow < 32u) {
                uint32_t dst = smem_u32(&s_feat[buf][c][r][4 + q * 4]);
                CP_ASYNC16(dst, featb + c * NPIX + grow * WW + q * 4);
            }
        }
        CP_COMMIT();
    };

    float accA[27], accB[27];
    #pragma unroll
    for (int i = 0; i < 27; ++i) { accA[i] = 0.f; accB[i] = 0.f; }

    prefetch(0, 0);

    for (int cc = 0; cc < 8; ++cc) {
        const int buf = cc & 1;
        if (cc < 7) { prefetch(cc + 1, buf ^ 1); cp_wait<1>(); }
        else        { cp_wait<0>(); }
        __syncthreads();

        const float* srcb = src + ((size_t)(b * CC + cbase + cc * 8)) * NPIX
                            + (size_t)y * WW + x0;
        #pragma unroll
        for (int c = 0; c < 8; ++c) {
            float2 fv = *(const float2*)(srcb + (size_t)c * NPIX);
            #pragma unroll
            for (int dy2 = 0; dy2 < 3; ++dy2) {
                const float* fr = &s_feat[buf][c][ty + dy2][x0];
                float f[10];
                #pragma unroll
                for (int q = 0; q < 5; ++q) {
                    float2 t = *(const float2*)&fr[2 * q];
                    f[2 * q] = t.x; f[2 * q + 1] = t.y;
                }
                #pragma unroll
                for (int dx = 0; dx < 9; ++dx) {
                    accA[dy2 * 9 + dx] = fmaf(fv.x, f[dx],     accA[dy2 * 9 + dx]);
                    accB[dy2 * 9 + dx] = fmaf(fv.y, f[dx + 1], accB[dy2 * 9 + dx]);
                }
            }
        }
        __syncthreads();
    }

    #pragma unroll
    for (int kk = 0; kk < 27; ++kk) {
        int kg = d0 * 9 + kk;
        size_t base = (((size_t)(slice * BB + b) * KK + kg) << 10) + (y << 5) + x0;
        *(float2*)&g_part[base] = make_float2(accA[kk], accB[kk]);
    }
}

// ---------------- combine A: activation, residuals, loss ----------------
__global__ __launch_bounds__(256)
void k_postA(int iter) {
    __shared__ float s_red[256];
    int idx = blockIdx.x * 256 + threadIdx.x;   // < 16*81*1024
    int p = idx & 1023;
    int t = idx >> 10;
    int b = t / KK;
    int k = t - b * KK;

    float s = 0.f;
    #pragma unroll
    for (int sl = 0; sl < NSLICE; ++sl)
        s += g_part[(((size_t)(sl * BB + b) * KK + k) << 10) + p];

    float m = g_m[k], w = g_w[k], lab = g_label[k];
    float cm = 0.5f * (1.0f - m), cp = 0.5f * (1.0f + m);
    float sgn = (s > 0.f) ? 1.0f : ((s < 0.f) ? -1.0f : 0.0f);
    float sact = cm * fabsf(s) + cp * s;
    float smask = cm * sgn + cp;
    float lr = w * (sact - lab);
    size_t base = (((size_t)b * KK + k) << 10) + p;
    g_mr[base] = smask * w * lr;
    g_wm[base] = w * smask;

    // block reduce lr^2
    int tid = threadIdx.x;
    s_red[tid] = lr * lr;
    __syncthreads();
    #pragma unroll
    for (int o = 128; o > 0; o >>= 1) {
        if (tid < o) s_red[tid] += s_red[tid + o];
        __syncthreads();
    }
    if (tid == 0) atomicAdd(&g_lr2[iter], s_red[0]);
}

// ---------------- combine B: scores_grad -> alpha_den ----------------
__global__ __launch_bounds__(256)
void k_postB() {
    int idx = blockIdx.x * 256 + threadIdx.x;
    int p = idx & 1023;
    int t = idx >> 10;
    int b = t / KK;
    int k = t - b * KK;

    float s = 0.f;
    #pragma unroll
    for (int sl = 0; sl < NSLICE; ++sl)
        s += g_part[(((size_t)(sl * BB + b) * KK + k) << 10) + p];

    float wm = g_wm[(((size_t)b * KK + k) << 10) + p];
    float sg = wm * s;
    atomicAdd(&g_alpha_den[(b << 10) + p], sg * sg);
}

// ---------------- transpose correlation: filter_grad ----------------
// Grid: (8 ytiles, 8 channel-splits, 16 batch). Block: 128 = 4 rows x 32 cols.
// Each thread owns one pixel with all 81 residuals in registers; 32 channels.
// feat staged via double-buffered cp.async.
__global__ __launch_bounds__(128)
void k_btrans(const float* __restrict__ flt, const float* __restrict__ feat, int iter) {
    __shared__ __align__(16) float s_feat[2][8][12][40];
    __shared__ float s_red[128];

    const int tid = threadIdx.x;
    const int tx = tid & 31;
    const int ty = tid >> 5;          // 0..3
    const int b  = blockIdx.z;
    const int cs = blockIdx.y;        // 0..7
    const int y0 = blockIdx.x * 4;
    const int y  = y0 + ty;
    const int x  = tx;

    const float rw = g_params[1];

    // pre-zero both buffers (halo rows/cols stay zero)
    {
        float* sf = &s_feat[0][0][0][0];
        for (int i = tid; i < 2 * 8 * 12 * 40; i += 128) sf[i] = 0.f;
    }

    float mrv[KK];
    #pragma unroll
    for (int k = 0; k < KK; ++k)
        mrv[k] = g_mr[(((size_t)b * KK + k) << 10) + (y << 5) + x];

    __syncthreads();

    auto prefetch = [&](int cc, int buf) {
        const float* featb = feat + ((size_t)(b * CC + cs * 32 + cc * 8)) * NPIX;
        #pragma unroll
        for (int j = 0; j < 6; ++j) {
            int i = tid + j * 128;        // 0..767
            int c = i / 96; int rem = i % 96;
            int r = rem >> 3; int q = rem & 7;
            int grow = y0 - 4 + r;
            if ((unsigned)grow < 32u) {
                uint32_t dst = smem_u32(&s_feat[buf][c][r][4 + q * 4]);
                CP_ASYNC16(dst, featb + c * NPIX + grow * WW + q * 4);
            }
        }
        CP_COMMIT();
    };

    float anum = 0.f, fl2 = 0.f;

    prefetch(0, 0);

    for (int cc = 0; cc < 4; ++cc) {
        const int buf = cc & 1;
        if (cc < 3) { prefetch(cc + 1, buf ^ 1); cp_wait<1>(); }
        else        { cp_wait<0>(); }
        __syncthreads();

        const int cbase = cs * 32 + cc * 8;
        #pragma unroll
        for (int c = 0; c < 8; ++c) {
            float g = 0.f;
            #pragma unroll
            for (int dy = 0; dy < 9; ++dy) {
                const float* fr = &s_feat[buf][c][ty + dy][tx];
                #pragma unroll
                for (int dx = 0; dx < 9; ++dx)
                    g = fmaf(mrv[dy * 9 + dx], fr[dx], g);
            }
            size_t gidx = (((size_t)(b * CC + cbase + c)) << 10) + (y << 5) + x;
            float fl = flt[gidx];
            g = fmaf(rw, fl, g);
            g_fgrad[gidx] = g;
            anum += g * g;
            fl2 += fl * fl;
        }
        __syncthreads();
    }

    atomicAdd(&g_alpha_num[(b << 10) + (y << 5) + x], anum);
    s_red[tid] = fl2;
    __syncthreads();
    #pragma unroll
    for (int o = 64; o > 0; o >>= 1) {
        if (tid < o) s_red[tid] += s_red[tid + o];
        __syncthreads();
    }
    if (tid == 0) atomicAdd(&g_flt2[iter], s_red[0]);
}

// ---------------- filter update ----------------
__global__ void k_update(float* __restrict__ flt) {
    int idx = blockIdx.x * 256 + threadIdx.x;
    float step = g_params[0], rw = g_params[1];
    int spix = idx & 1023;
    int b = idx >> 18;                 // / (256*1024)
    int p = (b << 10) + spix;
    float num = g_alpha_num[p];
    float den = g_alpha_den[p] + rw * num;
    den = fmaxf(den, 1e-8f);
    float alpha = num / den;
    flt[idx] -= step * alpha * g_fgrad[idx];
}

// ---------------- final scalars ----------------
__global__ void k_fin(float* __restrict__ out) {
    int i = threadIdx.x;
    if (i < 3) {
        float rw = g_params[1];
        float src = 0.5f * g_lr2[i] / (float)BB;
        float reg = 0.5f * rw * g_flt2[i] / (float)BB;
        out[FLT_ELEMS + i]     = src + reg;   // tr
        out[FLT_ELEMS + 3 + i] = src;         // tr_src
        out[FLT_ELEMS + 6 + i] = reg;         // tr_reg
    }
}

// ---------------- launch ----------------
extern "C" void kernel_launch(void* const* d_in, const int* in_sizes, int n_in,
                              void* d_out, int out_size) {
    const float* flt_in = (const float*)d_in[0];
    const float* feat   = (const float*)d_in[1];
    const float* lw     = (const float*)d_in[2];
    const float* mw     = (const float*)d_in[3];
    const float* sw     = (const float*)d_in[4];
    const float* lsl    = (const float*)d_in[5];
    const float* fr     = (const float*)d_in[6];
    float* out = (float*)d_out;

    size_t ncpy = (out_size < FLT_ELEMS) ? (size_t)out_size : (size_t)FLT_ELEMS;
    cudaMemcpyAsync(out, flt_in, ncpy * sizeof(float), cudaMemcpyDeviceToDevice);

    k_pre<<<1, 128>>>(lw, mw, sw, lsl, fr);

    const int POST_BLOCKS = (BB * KK * NPIX) / 256;   // 5184

    for (int it = 0; it < 3; ++it) {
        k_zero<<<64, 256>>>();
        k_corrP<<<dim3(12, NSLICE, BB), 128>>>(out, feat);
        k_postA<<<POST_BLOCKS, 256>>>(it);
        k_btrans<<<dim3(8, 8, BB), 128>>>(out, feat, it);
        k_corrP<<<dim3(12, NSLICE, BB), 128>>>(nullptr, feat);
        k_postB<<<POST_BLOCKS, 256>>>();
        k_update<<<FLT_ELEMS / 256, 256>>>(out);
    }

    if (out_size >= FLT_ELEMS + 9)
        k_fin<<<1, 32>>>(out);
}

// round 11
// speedup vs baseline: 3.2813x; 1.0696x over previous
#include <cuda_runtime.h>
#include <cstddef>
#include <cstdint>

// Problem constants
#define BB 16
#define CC 256
#define HH 32
#define WW 32
#define KK 81
#define PADR 4
#define NPIX (HH*WW)            // 1024
#define FLT_ELEMS (BB*CC*NPIX)  // 4194304

// ---------------- cp.async helpers ----------------
__device__ __forceinline__ uint32_t smem_u32(const void* p) {
    return (uint32_t)__cvta_generic_to_shared(p);
}
#define CP_ASYNC16(dst_u32, src_ptr) \
    asm volatile("cp.async.cg.shared.global [%0], [%1], 16;" :: "r"(dst_u32), "l"(src_ptr) : "memory")
#define CP_COMMIT() asm volatile("cp.async.commit_group;" ::: "memory")
template <int N>
__device__ __forceinline__ void cp_wait() {
    asm volatile("cp.async.wait_group %0;" :: "n"(N) : "memory");
}

// ---------------- device scratch (no allocation allowed) ----------------
__device__ __align__(16) float g_mr[BB*KK*NPIX];     // mapped residuals  [b,k,p]
__device__ __align__(16) float g_wm[BB*KK*NPIX];     // w * score_mask    [b,k,p]
__device__ __align__(16) float g_fgrad[FLT_ELEMS];   // filter gradient
__device__ float g_alpha_num[BB*NPIX];
__device__ float g_alpha_den[BB*NPIX];
__device__ float g_label[KK];
__device__ float g_m[KK];
__device__ float g_w[KK];
__device__ float g_params[2];      // [0]=step_length, [1]=reg_weight
__device__ float g_lr2[3];         // sum loss_residuals^2 per iter
__device__ float g_flt2[3];        // sum flt^2 per iter

// ---------------- precompute: distance-map projections ----------------
__global__ void k_pre(const float* __restrict__ label_w,
                      const float* __restrict__ mask_w,
                      const float* __restrict__ spatial_w,
                      const float* __restrict__ lsl,
                      const float* __restrict__ freg) {
    int k = threadIdx.x;
    if (k == 0) {
        g_params[0] = expf(lsl[0]);
        float r2 = freg[0] * freg[0];
        r2 = fmaxf(r2, 1e-10f);                 // clip at MIN_FILTER_REG^2
        g_params[1] = r2 / (256.0f * 256.0f);   // / feat_dim^2
        for (int i = 0; i < 3; ++i) { g_lr2[i] = 0.f; g_flt2[i] = 0.f; }
    }
    if (k < KK) {
        int i = k / 9, j = k % 9;
        float di = (float)(i - PADR), dj = (float)(j - PADR);
        float dist = sqrtf(di * di + dj * dj);
        float lab = 0.f, ml = 0.f, sw = 0.f;
        #pragma unroll
        for (int d = 0; d < 10; ++d) {
            float bd = dist * 2.0f - (float)d;   // dist / 0.5 - d
            float bv;
            if (d < 9) bv = fmaxf(1.0f - fabsf(bd), 0.0f);
            else       bv = fminf(fmaxf(1.0f + bd, 0.0f), 1.0f);
            lab += bv * label_w[d];
            ml  += bv * mask_w[d];
            sw  += bv * spatial_w[d];
        }
        g_label[k] = lab;
        g_m[k]     = 1.0f / (1.0f + expf(-ml));
        g_w[k]     = sw;
    }
}

// ---------------- zero per-iteration accumulators ----------------
__global__ void k_zero() {
    int idx = blockIdx.x * blockDim.x + threadIdx.x;
    if (idx < BB * NPIX) { g_alpha_num[idx] = 0.f; g_alpha_den[idx] = 0.f; }
}

// ---------------- fused correlation kernel ----------------
// Grid: dim3(36, 1, 16): blockIdx.x = dy*4 + ytile (dy 0..8, ytile 0..3), z = batch.
// Block 128 = 8 rows x 16 pixel-pairs. Each thread owns 2 adjacent x pixels and
// 9 k-channels (fixed dy, dx 0..8). Reduces ALL 256 channels (32 chunks of 8),
// feat double-buffered via cp.async, src read directly (no reuse).
// IS_A=true : src = filter; epilogue computes activation -> g_mr/g_wm, loss sum.
// IS_A=false: src = g_fgrad; epilogue computes wm*s -> alpha_den atomics.
template <bool IS_A>
__global__ __launch_bounds__(128)
void k_corrF(const float* __restrict__ srcp, const float* __restrict__ feat, int iter) {
    __shared__ __align__(16) float s_feat[2][8][8][40];
    __shared__ float s_red[128];

    const int tid = threadIdx.x;
    const int ty = tid >> 4;          // 0..7
    const int txq = tid & 15;         // 0..15
    const int dy = blockIdx.x >> 2;   // 0..8
    const int ytile = blockIdx.x & 3; // 0..3
    const int b  = blockIdx.z;
    const int y0 = ytile * 8;
    const int y  = y0 + ty;
    const int x0 = 2 * txq;
    const int row0 = y0 + dy - 4;     // first feat row staged

    const float* src = IS_A ? srcp : g_fgrad;

    // pre-zero both buffers (halo cols / OOB rows stay zero through all chunks)
    {
        float* sf = &s_feat[0][0][0][0];
        for (int i = tid; i < 2 * 8 * 8 * 40; i += 128) sf[i] = 0.f;
    }
    __syncthreads();

    // prefetch chunk cc -> buffer buf: 8 channels x 8 rows x 32 interior cols
    auto prefetch = [&](int cc, int buf) {
        const float* featb = feat + ((size_t)(b * CC + cc * 8)) * NPIX;
        #pragma unroll
        for (int j = 0; j < 4; ++j) {
            int i = tid + j * 128;    // 0..511
            int c = i >> 6;           // 0..7
            int rem = i & 63;
            int r = rem >> 3; int q = rem & 7;
            int grow = row0 + r;
            if ((unsigned)grow < 32u) {
                uint32_t dst = smem_u32(&s_feat[buf][c][r][4 + q * 4]);
                CP_ASYNC16(dst, featb + c * NPIX + grow * WW + q * 4);
            }
        }
        CP_COMMIT();
    };

    float accA[9], accB[9];
    #pragma unroll
    for (int i = 0; i < 9; ++i) { accA[i] = 0.f; accB[i] = 0.f; }

    prefetch(0, 0);

    for (int cc = 0; cc < 32; ++cc) {
        const int buf = cc & 1;
        if (cc < 31) { prefetch(cc + 1, buf ^ 1); cp_wait<1>(); }
        else         { cp_wait<0>(); }
        __syncthreads();

        const float* srcb = src + ((size_t)(b * CC + cc * 8)) * NPIX
                            + (size_t)y * WW + x0;
        #pragma unroll
        for (int c = 0; c < 8; ++c) {
            float2 fv = *(const float2*)(srcb + (size_t)c * NPIX);
            const float* fr = &s_feat[buf][c][ty][x0];
            float f[10];
            #pragma unroll
            for (int q = 0; q < 5; ++q) {
                float2 t = *(const float2*)&fr[2 * q];
                f[2 * q] = t.x; f[2 * q + 1] = t.y;
            }
            #pragma unroll
            for (int dx = 0; dx < 9; ++dx) {
                accA[dx] = fmaf(fv.x, f[dx],     accA[dx]);
                accB[dx] = fmaf(fv.y, f[dx + 1], accB[dx]);
            }
        }
        __syncthreads();
    }

    if (IS_A) {
        float lsum = 0.f;
        #pragma unroll
        for (int dx = 0; dx < 9; ++dx) {
            int k = dy * 9 + dx;
            float m = g_m[k], w = g_w[k], lab = g_label[k];
            float cm = 0.5f * (1.0f - m), cp = 0.5f * (1.0f + m);

            float sA = accA[dx];
            float sgnA = (sA > 0.f) ? 1.0f : ((sA < 0.f) ? -1.0f : 0.0f);
            float sactA = cm * fabsf(sA) + cp * sA;
            float smaskA = cm * sgnA + cp;
            float lrA = w * (sactA - lab);

            float sB = accB[dx];
            float sgnB = (sB > 0.f) ? 1.0f : ((sB < 0.f) ? -1.0f : 0.0f);
            float sactB = cm * fabsf(sB) + cp * sB;
            float smaskB = cm * sgnB + cp;
            float lrB = w * (sactB - lab);

            size_t base = (((size_t)b * KK + k) << 10) + (y << 5) + x0;
            *(float2*)&g_mr[base] = make_float2(smaskA * w * lrA, smaskB * w * lrB);
            *(float2*)&g_wm[base] = make_float2(w * smaskA, w * smaskB);
            lsum += lrA * lrA + lrB * lrB;
        }
        s_red[tid] = lsum;
        __syncthreads();
        #pragma unroll
        for (int o = 64; o > 0; o >>= 1) {
            if (tid < o) s_red[tid] += s_red[tid + o];
            __syncthreads();
        }
        if (tid == 0) atomicAdd(&g_lr2[iter], s_red[0]);
    } else {
        float denA = 0.f, denB = 0.f;
        #pragma unroll
        for (int dx = 0; dx < 9; ++dx) {
            int k = dy * 9 + dx;
            size_t base = (((size_t)b * KK + k) << 10) + (y << 5) + x0;
            float2 wm2 = *(const float2*)&g_wm[base];
            float sgA = wm2.x * accA[dx];
            float sgB = wm2.y * accB[dx];
            denA += sgA * sgA;
            denB += sgB * sgB;
        }
        int p = (b << 10) + (y << 5) + x0;
        atomicAdd(&g_alpha_den[p], denA);
        atomicAdd(&g_alpha_den[p + 1], denB);
    }
}

// ---------------- transpose correlation: filter_grad ----------------
// Grid: (8 ytiles, 8 channel-splits, 16 batch). Block: 128 = 4 rows x 32 cols.
// Each thread owns one pixel with all 81 residuals in registers; 32 channels.
// feat staged via double-buffered cp.async.
__global__ __launch_bounds__(128)
void k_btrans(const float* __restrict__ flt, const float* __restrict__ feat, int iter) {
    __shared__ __align__(16) float s_feat[2][8][12][40];
    __shared__ float s_red[128];

    const int tid = threadIdx.x;
    const int tx = tid & 31;
    const int ty = tid >> 5;          // 0..3
    const int b  = blockIdx.z;
    const int cs = blockIdx.y;        // 0..7
    const int y0 = blockIdx.x * 4;
    const int y  = y0 + ty;
    const int x  = tx;

    const float rw = g_params[1];

    // pre-zero both buffers (halo rows/cols stay zero)
    {
        float* sf = &s_feat[0][0][0][0];
        for (int i = tid; i < 2 * 8 * 12 * 40; i += 128) sf[i] = 0.f;
    }

    float mrv[KK];
    #pragma unroll
    for (int k = 0; k < KK; ++k)
        mrv[k] = g_mr[(((size_t)b * KK + k) << 10) + (y << 5) + x];

    __syncthreads();

    auto prefetch = [&](int cc, int buf) {
        const float* featb = feat + ((size_t)(b * CC + cs * 32 + cc * 8)) * NPIX;
        #pragma unroll
        for (int j = 0; j < 6; ++j) {
            int i = tid + j * 128;        // 0..767
            int c = i / 96; int rem = i % 96;
            int r = rem >> 3; int q = rem & 7;
            int grow = y0 - 4 + r;
            if ((unsigned)grow < 32u) {
                uint32_t dst = smem_u32(&s_feat[buf][c][r][4 + q * 4]);
                CP_ASYNC16(dst, featb + c * NPIX + grow * WW + q * 4);
            }
        }
        CP_COMMIT();
    };

    float anum = 0.f, fl2 = 0.f;

    prefetch(0, 0);

    for (int cc = 0; cc < 4; ++cc) {
        const int buf = cc & 1;
        if (cc < 3) { prefetch(cc + 1, buf ^ 1); cp_wait<1>(); }
        else        { cp_wait<0>(); }
        __syncthreads();

        const int cbase = cs * 32 + cc * 8;
        #pragma unroll
        for (int c = 0; c < 8; ++c) {
            float g = 0.f;
            #pragma unroll
            for (int dy = 0; dy < 9; ++dy) {
                const float* fr = &s_feat[buf][c][ty + dy][tx];
                #pragma unroll
                for (int dx = 0; dx < 9; ++dx)
                    g = fmaf(mrv[dy * 9 + dx], fr[dx], g);
            }
            size_t gidx = (((size_t)(b * CC + cbase + c)) << 10) + (y << 5) + x;
            float fl = flt[gidx];
            g = fmaf(rw, fl, g);
            g_fgrad[gidx] = g;
            anum += g * g;
            fl2 += fl * fl;
        }
        __syncthreads();
    }

    atomicAdd(&g_alpha_num[(b << 10) + (y << 5) + x], anum);
    s_red[tid] = fl2;
    __syncthreads();
    #pragma unroll
    for (int o = 64; o > 0; o >>= 1) {
        if (tid < o) s_red[tid] += s_red[tid + o];
        __syncthreads();
    }
    if (tid == 0) atomicAdd(&g_flt2[iter], s_red[0]);
}

// ---------------- filter update ----------------
__global__ void k_update(float* __restrict__ flt) {
    int idx = blockIdx.x * 256 + threadIdx.x;
    float step = g_params[0], rw = g_params[1];
    int spix = idx & 1023;
    int b = idx >> 18;                 // / (256*1024)
    int p = (b << 10) + spix;
    float num = g_alpha_num[p];
    float den = g_alpha_den[p] + rw * num;
    den = fmaxf(den, 1e-8f);
    float alpha = num / den;
    flt[idx] -= step * alpha * g_fgrad[idx];
}

// ---------------- final scalars ----------------
__global__ void k_fin(float* __restrict__ out) {
    int i = threadIdx.x;
    if (i < 3) {
        float rw = g_params[1];
        float src = 0.5f * g_lr2[i] / (float)BB;
        float reg = 0.5f * rw * g_flt2[i] / (float)BB;
        out[FLT_ELEMS + i]     = src + reg;   // tr
        out[FLT_ELEMS + 3 + i] = src;         // tr_src
        out[FLT_ELEMS + 6 + i] = reg;         // tr_reg
    }
}

// ---------------- launch ----------------
extern "C" void kernel_launch(void* const* d_in, const int* in_sizes, int n_in,
                              void* d_out, int out_size) {
    const float* flt_in = (const float*)d_in[0];
    const float* feat   = (const float*)d_in[1];
    const float* lw     = (const float*)d_in[2];
    const float* mw     = (const float*)d_in[3];
    const float* sw     = (const float*)d_in[4];
    const float* lsl    = (const float*)d_in[5];
    const float* fr     = (const float*)d_in[6];
    float* out = (float*)d_out;

    size_t ncpy = (out_size < FLT_ELEMS) ? (size_t)out_size : (size_t)FLT_ELEMS;
    cudaMemcpyAsync(out, flt_in, ncpy * sizeof(float), cudaMemcpyDeviceToDevice);

    k_pre<<<1, 128>>>(lw, mw, sw, lsl, fr);

    for (int it = 0; it < 3; ++it) {
        k_zero<<<64, 256>>>();
        k_corrF<true><<<dim3(36, 1, BB), 128>>>(out, feat, it);
        k_btrans<<<dim3(8, 8, BB), 128>>>(out, feat, it);
        k_corrF<false><<<dim3(36, 1, BB), 128>>>(nullptr, feat, it);
        k_update<<<FLT_ELEMS / 256, 256>>>(out);
    }

    if (out_size >= FLT_ELEMS + 9)
        k_fin<<<1, 32>>>(out);
}

// round 12
// speedup vs baseline: 3.4622x; 1.0551x over previous
#include <cuda_runtime.h>
#include <cstddef>
#include <cstdint>

// Problem constants
#define BB 16
#define CC 256
#define HH 32
#define WW 32
#define KK 81
#define PADR 4
#define NPIX (HH*WW)            // 1024
#define FLT_ELEMS (BB*CC*NPIX)  // 4194304

// ---------------- cp.async helpers ----------------
__device__ __forceinline__ uint32_t smem_u32(const void* p) {
    return (uint32_t)__cvta_generic_to_shared(p);
}
#define CP_ASYNC16(dst_u32, src_ptr) \
    asm volatile("cp.async.cg.shared.global [%0], [%1], 16;" :: "r"(dst_u32), "l"(src_ptr) : "memory")
#define CP_COMMIT() asm volatile("cp.async.commit_group;" ::: "memory")
template <int N>
__device__ __forceinline__ void cp_wait() {
    asm volatile("cp.async.wait_group %0;" :: "n"(N) : "memory");
}

// ---------------- device scratch (no allocation allowed) ----------------
__device__ __align__(16) float g_mr[BB*KK*NPIX];     // mapped residuals  [b,k,p]
__device__ __align__(16) float g_wm[BB*KK*NPIX];     // w * score_mask    [b,k,p]
__device__ __align__(16) float g_fgrad[FLT_ELEMS];   // filter gradient
__device__ float g_alpha_num[BB*NPIX];
__device__ float g_alpha_den[BB*NPIX];
__device__ float g_label[KK];
__device__ float g_m[KK];
__device__ float g_w[KK];
__device__ float g_params[2];      // [0]=step_length, [1]=reg_weight
__device__ float g_lr2[3];         // sum loss_residuals^2 per iter
__device__ float g_flt2[3];        // sum flt^2 per iter

// ---------------- precompute: distance-map projections ----------------
__global__ void k_pre(const float* __restrict__ label_w,
                      const float* __restrict__ mask_w,
                      const float* __restrict__ spatial_w,
                      const float* __restrict__ lsl,
                      const float* __restrict__ freg) {
    int k = threadIdx.x;
    if (k == 0) {
        g_params[0] = expf(lsl[0]);
        float r2 = freg[0] * freg[0];
        r2 = fmaxf(r2, 1e-10f);                 // clip at MIN_FILTER_REG^2
        g_params[1] = r2 / (256.0f * 256.0f);   // / feat_dim^2
        for (int i = 0; i < 3; ++i) { g_lr2[i] = 0.f; g_flt2[i] = 0.f; }
    }
    if (k < KK) {
        int i = k / 9, j = k % 9;
        float di = (float)(i - PADR), dj = (float)(j - PADR);
        float dist = sqrtf(di * di + dj * dj);
        float lab = 0.f, ml = 0.f, sw = 0.f;
        #pragma unroll
        for (int d = 0; d < 10; ++d) {
            float bd = dist * 2.0f - (float)d;   // dist / 0.5 - d
            float bv;
            if (d < 9) bv = fmaxf(1.0f - fabsf(bd), 0.0f);
            else       bv = fminf(fmaxf(1.0f + bd, 0.0f), 1.0f);
            lab += bv * label_w[d];
            ml  += bv * mask_w[d];
            sw  += bv * spatial_w[d];
        }
        g_label[k] = lab;
        g_m[k]     = 1.0f / (1.0f + expf(-ml));
        g_w[k]     = sw;
    }
}

// ---------------- zero per-iteration accumulators ----------------
__global__ void k_zero() {
    int idx = blockIdx.x * blockDim.x + threadIdx.x;
    if (idx < BB * NPIX) { g_alpha_num[idx] = 0.f; g_alpha_den[idx] = 0.f; }
}

// ---------------- fused correlation kernel ----------------
// Grid: dim3(72, 1, 16): blockIdx.x = dy*8 + ytile (dy 0..8, ytile 0..7), z = batch.
// Block 64 = 4 rows x 16 pixel-pairs. Each thread: 2 adjacent x pixels, 9 k-channels
// (fixed dy, dx 0..8). Reduces ALL 256 channels (32 chunks of 8), feat double-buffered
// via cp.async, src read directly.
// IS_A=true : src = filter; epilogue computes activation -> g_mr/g_wm, loss sum.
// IS_A=false: src = g_fgrad; epilogue computes wm*s -> alpha_den atomics.
template <bool IS_A>
__global__ __launch_bounds__(64)
void k_corrF(const float* __restrict__ srcp, const float* __restrict__ feat, int iter) {
    __shared__ __align__(16) float s_feat[2][8][4][40];
    __shared__ float s_red[64];

    const int tid = threadIdx.x;
    const int ty = tid >> 4;          // 0..3
    const int txq = tid & 15;         // 0..15
    const int dy = blockIdx.x >> 3;   // 0..8
    const int ytile = blockIdx.x & 7; // 0..7
    const int b  = blockIdx.z;
    const int y0 = ytile * 4;
    const int y  = y0 + ty;
    const int x0 = 2 * txq;
    const int row0 = y0 + dy - 4;     // first feat row staged (4 rows)

    const float* src = IS_A ? srcp : g_fgrad;

    // pre-zero both buffers (halo cols / OOB rows stay zero through all chunks)
    {
        float* sf = &s_feat[0][0][0][0];
        for (int i = tid; i < 2 * 8 * 4 * 40; i += 64) sf[i] = 0.f;
    }
    __syncthreads();

    // prefetch chunk cc -> buffer buf: 8 channels x 4 rows x 32 interior cols
    auto prefetch = [&](int cc, int buf) {
        const float* featb = feat + ((size_t)(b * CC + cc * 8)) * NPIX;
        #pragma unroll
        for (int j = 0; j < 4; ++j) {
            int i = tid + j * 64;     // 0..255
            int c = i >> 5;           // 0..7
            int rem = i & 31;
            int r = rem >> 3; int q = rem & 7;
            int grow = row0 + r;
            if ((unsigned)grow < 32u) {
                uint32_t dst = smem_u32(&s_feat[buf][c][r][4 + q * 4]);
                CP_ASYNC16(dst, featb + c * NPIX + grow * WW + q * 4);
            }
        }
        CP_COMMIT();
    };

    float accA[9], accB[9];
    #pragma unroll
    for (int i = 0; i < 9; ++i) { accA[i] = 0.f; accB[i] = 0.f; }

    prefetch(0, 0);

    for (int cc = 0; cc < 32; ++cc) {
        const int buf = cc & 1;
        if (cc < 31) { prefetch(cc + 1, buf ^ 1); cp_wait<1>(); }
        else         { cp_wait<0>(); }
        __syncthreads();

        const float* srcb = src + ((size_t)(b * CC + cc * 8)) * NPIX
                            + (size_t)y * WW + x0;
        #pragma unroll
        for (int c = 0; c < 8; ++c) {
            float2 fv = *(const float2*)(srcb + (size_t)c * NPIX);
            const float* fr = &s_feat[buf][c][ty][x0];
            float f[10];
            #pragma unroll
            for (int q = 0; q < 5; ++q) {
                float2 t = *(const float2*)&fr[2 * q];
                f[2 * q] = t.x; f[2 * q + 1] = t.y;
            }
            #pragma unroll
            for (int dx = 0; dx < 9; ++dx) {
                accA[dx] = fmaf(fv.x, f[dx],     accA[dx]);
                accB[dx] = fmaf(fv.y, f[dx + 1], accB[dx]);
            }
        }
        __syncthreads();
    }

    if (IS_A) {
        float lsum = 0.f;
        #pragma unroll
        for (int dx = 0; dx < 9; ++dx) {
            int k = dy * 9 + dx;
            float m = g_m[k], w = g_w[k], lab = g_label[k];
            float cm = 0.5f * (1.0f - m), cp = 0.5f * (1.0f + m);

            float sA = accA[dx];
            float sgnA = (sA > 0.f) ? 1.0f : ((sA < 0.f) ? -1.0f : 0.0f);
            float sactA = cm * fabsf(sA) + cp * sA;
            float smaskA = cm * sgnA + cp;
            float lrA = w * (sactA - lab);

            float sB = accB[dx];
            float sgnB = (sB > 0.f) ? 1.0f : ((sB < 0.f) ? -1.0f : 0.0f);
            float sactB = cm * fabsf(sB) + cp * sB;
            float smaskB = cm * sgnB + cp;
            float lrB = w * (sactB - lab);

            size_t base = (((size_t)b * KK + k) << 10) + (y << 5) + x0;
            *(float2*)&g_mr[base] = make_float2(smaskA * w * lrA, smaskB * w * lrB);
            *(float2*)&g_wm[base] = make_float2(w * smaskA, w * smaskB);
            lsum += lrA * lrA + lrB * lrB;
        }
        s_red[tid] = lsum;
        __syncthreads();
        #pragma unroll
        for (int o = 32; o > 0; o >>= 1) {
            if (tid < o) s_red[tid] += s_red[tid + o];
            __syncthreads();
        }
        if (tid == 0) atomicAdd(&g_lr2[iter], s_red[0]);
    } else {
        float denA = 0.f, denB = 0.f;
        #pragma unroll
        for (int dx = 0; dx < 9; ++dx) {
            int k = dy * 9 + dx;
            size_t base = (((size_t)b * KK + k) << 10) + (y << 5) + x0;
            float2 wm2 = *(const float2*)&g_wm[base];
            float sgA = wm2.x * accA[dx];
            float sgB = wm2.y * accB[dx];
            denA += sgA * sgA;
            denB += sgB * sgB;
        }
        int p = (b << 10) + (y << 5) + x0;
        atomicAdd(&g_alpha_den[p], denA);
        atomicAdd(&g_alpha_den[p + 1], denB);
    }
}

// ---------------- transpose correlation: filter_grad, dy-split 2-pass ----------------
// Grid: (8 ytiles, 8 channel-splits, 16 batch). Block: 128 = 4 rows x 32 cols.
// PASS=0: dy 0..4 (45 residual regs), writes partial g to g_fgrad.
// PASS=1: dy 5..8 (36 regs), adds partial + reg term, writes final g,
//         accumulates alpha_num and flt^2.
// Staged feat rows r=0..7 map to global rows (PASS?y0+1:y0-4)+r; compute index r=ty+ldy.
template <int PASS>
__global__ __launch_bounds__(128)
void k_btrans(const float* __restrict__ flt, const float* __restrict__ feat, int iter) {
    constexpr int DY0 = PASS ? 5 : 0;
    constexpr int NDY = PASS ? 4 : 5;
    constexpr int RB  = PASS ? 1 : -4;   // staged row base offset from y0

    __shared__ __align__(16) float s_feat[2][8][8][40];
    __shared__ float s_red[128];

    const int tid = threadIdx.x;
    const int tx = tid & 31;
    const int ty = tid >> 5;          // 0..3
    const int b  = blockIdx.z;
    const int cs = blockIdx.y;        // 0..7
    const int y0 = blockIdx.x * 4;
    const int y  = y0 + ty;
    const int x  = tx;

    const float rw = g_params[1];

    // pre-zero both buffers (halo rows/cols stay zero)
    {
        float* sf = &s_feat[0][0][0][0];
        for (int i = tid; i < 2 * 8 * 8 * 40; i += 128) sf[i] = 0.f;
    }

    float mrv[NDY * 9];
    #pragma unroll
    for (int k = 0; k < NDY * 9; ++k)
        mrv[k] = g_mr[(((size_t)b * KK + DY0 * 9 + k) << 10) + (y << 5) + x];

    __syncthreads();

    auto prefetch = [&](int cc, int buf) {
        const float* featb = feat + ((size_t)(b * CC + cs * 32 + cc * 8)) * NPIX;
        #pragma unroll
        for (int j = 0; j < 4; ++j) {
            int i = tid + j * 128;        // 0..511
            int c = i >> 6;               // 0..7
            int rem = i & 63;
            int r = rem >> 3; int q = rem & 7;
            int grow = y0 + RB + r;
            if ((unsigned)grow < 32u) {
                uint32_t dst = smem_u32(&s_feat[buf][c][r][4 + q * 4]);
                CP_ASYNC16(dst, featb + c * NPIX + grow * WW + q * 4);
            }
        }
        CP_COMMIT();
    };

    float anum = 0.f, fl2 = 0.f;

    prefetch(0, 0);

    for (int cc = 0; cc < 4; ++cc) {
        const int buf = cc & 1;
        if (cc < 3) { prefetch(cc + 1, buf ^ 1); cp_wait<1>(); }
        else        { cp_wait<0>(); }
        __syncthreads();

        const int cbase = cs * 32 + cc * 8;
        #pragma unroll
        for (int c = 0; c < 8; ++c) {
            float g = 0.f;
            #pragma unroll
            for (int ldy = 0; ldy < NDY; ++ldy) {
                const float* fr = &s_feat[buf][c][ty + ldy][tx];
                #pragma unroll
                for (int dx = 0; dx < 9; ++dx)
                    g = fmaf(mrv[ldy * 9 + dx], fr[dx], g);
            }
            size_t gidx = (((size_t)(b * CC + cbase + c)) << 10) + (y << 5) + x;
            if (PASS == 0) {
                g_fgrad[gidx] = g;
            } else {
                float fl = flt[gidx];
                g += g_fgrad[gidx];
                g = fmaf(rw, fl, g);
                g_fgrad[gidx] = g;
                anum += g * g;
                fl2 += fl * fl;
            }
        }
        __syncthreads();
    }

    if (PASS == 1) {
        atomicAdd(&g_alpha_num[(b << 10) + (y << 5) + x], anum);
        s_red[tid] = fl2;
        __syncthreads();
        #pragma unroll
        for (int o = 64; o > 0; o >>= 1) {
            if (tid < o) s_red[tid] += s_red[tid + o];
            __syncthreads();
        }
        if (tid == 0) atomicAdd(&g_flt2[iter], s_red[0]);
    }
}

// ---------------- filter update ----------------
__global__ void k_update(float* __restrict__ flt) {
    int idx = blockIdx.x * 256 + threadIdx.x;
    float step = g_params[0], rw = g_params[1];
    int spix = idx & 1023;
    int b = idx >> 18;                 // / (256*1024)
    int p = (b << 10) + spix;
    float num = g_alpha_num[p];
    float den = g_alpha_den[p] + rw * num;
    den = fmaxf(den, 1e-8f);
    float alpha = num / den;
    flt[idx] -= step * alpha * g_fgrad[idx];
}

// ---------------- final scalars ----------------
__global__ void k_fin(float* __restrict__ out) {
    int i = threadIdx.x;
    if (i < 3) {
        float rw = g_params[1];
        float src = 0.5f * g_lr2[i] / (float)BB;
        float reg = 0.5f * rw * g_flt2[i] / (float)BB;
        out[FLT_ELEMS + i]     = src + reg;   // tr
        out[FLT_ELEMS + 3 + i] = src;         // tr_src
        out[FLT_ELEMS + 6 + i] = reg;         // tr_reg
    }
}

// ---------------- launch ----------------
extern "C" void kernel_launch(void* const* d_in, const int* in_sizes, int n_in,
                              void* d_out, int out_size) {
    const float* flt_in = (const float*)d_in[0];
    const float* feat   = (const float*)d_in[1];
    const float* lw     = (const float*)d_in[2];
    const float* mw     = (const float*)d_in[3];
    const float* sw     = (const float*)d_in[4];
    const float* lsl    = (const float*)d_in[5];
    const float* fr     = (const float*)d_in[6];
    float* out = (float*)d_out;

    size_t ncpy = (out_size < FLT_ELEMS) ? (size_t)out_size : (size_t)FLT_ELEMS;
    cudaMemcpyAsync(out, flt_in, ncpy * sizeof(float), cudaMemcpyDeviceToDevice);

    k_pre<<<1, 128>>>(lw, mw, sw, lsl, fr);

    for (int it = 0; it < 3; ++it) {
        k_zero<<<64, 256>>>();
        k_corrF<true><<<dim3(72, 1, BB), 64>>>(out, feat, it);
        k_btrans<0><<<dim3(8, 8, BB), 128>>>(out, feat, it);
        k_btrans<1><<<dim3(8, 8, BB), 128>>>(out, feat, it);
        k_corrF<false><<<dim3(72, 1, BB), 64>>>(nullptr, feat, it);
        k_update<<<FLT_ELEMS / 256, 256>>>(out);
    }

    if (out_size >= FLT_ELEMS + 9)
        k_fin<<<1, 32>>>(out);
}

// round 14
// speedup vs baseline: 3.8300x; 1.1062x over previous
#include <cuda_runtime.h>
#include <cstddef>
#include <cstdint>

// Problem constants
#define BB 16
#define CC 256
#define HH 32
#define WW 32
#define KK 81
#define PADR 4
#define NPIX (HH*WW)            // 1024
#define FLT_ELEMS (BB*CC*NPIX)  // 4194304

// ---------------- cp.async helpers ----------------
__device__ __forceinline__ uint32_t smem_u32(const void* p) {
    return (uint32_t)__cvta_generic_to_shared(p);
}
#define CP_ASYNC16(dst_u32, src_ptr) \
    asm volatile("cp.async.cg.shared.global [%0], [%1], 16;" :: "r"(dst_u32), "l"(src_ptr) : "memory")
#define CP_COMMIT() asm volatile("cp.async.commit_group;" ::: "memory")
template <int N>
__device__ __forceinline__ void cp_wait() {
    asm volatile("cp.async.wait_group %0;" :: "n"(N) : "memory");
}

// ---------------- device scratch (no allocation allowed) ----------------
__device__ __align__(16) float g_mr[BB*KK*NPIX];     // mapped residuals  [b,k,p]
__device__ __align__(16) float g_wm[BB*KK*NPIX];     // w * score_mask    [b,k,p]
__device__ __align__(16) float g_fgrad[FLT_ELEMS];   // filter gradient
__device__ float g_alpha_num[BB*NPIX];
__device__ float g_alpha_den[BB*NPIX];
__device__ float g_label[KK];
__device__ float g_m[KK];
__device__ float g_w[KK];
__device__ float g_params[2];      // [0]=step_length, [1]=reg_weight
__device__ float g_lr2[3];         // sum loss_residuals^2 per iter
__device__ float g_flt2[3];        // sum flt^2 per iter

// ---------------- precompute: distance-map projections ----------------
__global__ void k_pre(const float* __restrict__ label_w,
                      const float* __restrict__ mask_w,
                      const float* __restrict__ spatial_w,
                      const float* __restrict__ lsl,
                      const float* __restrict__ freg) {
    int k = threadIdx.x;
    if (k == 0) {
        g_params[0] = expf(lsl[0]);
        float r2 = freg[0] * freg[0];
        r2 = fmaxf(r2, 1e-10f);                 // clip at MIN_FILTER_REG^2
        g_params[1] = r2 / (256.0f * 256.0f);   // / feat_dim^2
        for (int i = 0; i < 3; ++i) { g_lr2[i] = 0.f; g_flt2[i] = 0.f; }
    }
    if (k < KK) {
        int i = k / 9, j = k % 9;
        float di = (float)(i - PADR), dj = (float)(j - PADR);
        float dist = sqrtf(di * di + dj * dj);
        float lab = 0.f, ml = 0.f, sw = 0.f;
        #pragma unroll
        for (int d = 0; d < 10; ++d) {
            float bd = dist * 2.0f - (float)d;   // dist / 0.5 - d
            float bv;
            if (d < 9) bv = fmaxf(1.0f - fabsf(bd), 0.0f);
            else       bv = fminf(fmaxf(1.0f + bd, 0.0f), 1.0f);
            lab += bv * label_w[d];
            ml  += bv * mask_w[d];
            sw  += bv * spatial_w[d];
        }
        g_label[k] = lab;
        g_m[k]     = 1.0f / (1.0f + expf(-ml));
        g_w[k]     = sw;
    }
}

// ---------------- zero per-iteration accumulators ----------------
__global__ void k_zero() {
    int idx = blockIdx.x * blockDim.x + threadIdx.x;
    if (idx < BB * NPIX) { g_alpha_num[idx] = 0.f; g_alpha_den[idx] = 0.f; }
}

// ---------------- fused correlation kernel ----------------
// Grid: dim3(72, 1, 16): blockIdx.x = dy*8 + ytile (dy 0..8, ytile 0..7), z = batch.
// Block 64 = 4 rows x 16 pixel-pairs. Each thread: 2 adjacent x pixels, 9 k-channels
// (fixed dy, dx 0..8). Reduces ALL 256 channels (32 chunks of 8), feat double-buffered
// via cp.async, src read directly.
// IS_A=true : src = filter; epilogue computes activation -> g_mr/g_wm, loss sum.
// IS_A=false: src = g_fgrad; epilogue computes wm*s -> alpha_den atomics.
template <bool IS_A>
__global__ __launch_bounds__(64)
void k_corrF(const float* __restrict__ srcp, const float* __restrict__ feat, int iter) {
    __shared__ __align__(16) float s_feat[2][8][4][40];
    __shared__ float s_red[64];

    const int tid = threadIdx.x;
    const int ty = tid >> 4;          // 0..3
    const int txq = tid & 15;         // 0..15
    const int dy = blockIdx.x >> 3;   // 0..8
    const int ytile = blockIdx.x & 7; // 0..7
    const int b  = blockIdx.z;
    const int y0 = ytile * 4;
    const int y  = y0 + ty;
    const int x0 = 2 * txq;
    const int row0 = y0 + dy - 4;     // first feat row staged (4 rows)

    const float* src = IS_A ? srcp : g_fgrad;

    // pre-zero both buffers (halo cols / OOB rows stay zero through all chunks)
    {
        float* sf = &s_feat[0][0][0][0];
        for (int i = tid; i < 2 * 8 * 4 * 40; i += 64) sf[i] = 0.f;
    }
    __syncthreads();

    // prefetch chunk cc -> buffer buf: 8 channels x 4 rows x 32 interior cols
    auto prefetch = [&](int cc, int buf) {
        const float* featb = feat + ((size_t)(b * CC + cc * 8)) * NPIX;
        #pragma unroll
        for (int j = 0; j < 4; ++j) {
            int i = tid + j * 64;     // 0..255
            int c = i >> 5;           // 0..7
            int rem = i & 31;
            int r = rem >> 3; int q = rem & 7;
            int grow = row0 + r;
            if ((unsigned)grow < 32u) {
                uint32_t dst = smem_u32(&s_feat[buf][c][r][4 + q * 4]);
                CP_ASYNC16(dst, featb + c * NPIX + grow * WW + q * 4);
            }
        }
        CP_COMMIT();
    };

    float accA[9], accB[9];
    #pragma unroll
    for (int i = 0; i < 9; ++i) { accA[i] = 0.f; accB[i] = 0.f; }

    prefetch(0, 0);

    for (int cc = 0; cc < 32; ++cc) {
        const int buf = cc & 1;
        if (cc < 31) { prefetch(cc + 1, buf ^ 1); cp_wait<1>(); }
        else         { cp_wait<0>(); }
        __syncthreads();

        const float* srcb = src + ((size_t)(b * CC + cc * 8)) * NPIX
                            + (size_t)y * WW + x0;
        #pragma unroll
        for (int c = 0; c < 8; ++c) {
            float2 fv = *(const float2*)(srcb + (size_t)c * NPIX);
            const float* fr = &s_feat[buf][c][ty][x0];
            float f[10];
            #pragma unroll
            for (int q = 0; q < 5; ++q) {
                float2 t = *(const float2*)&fr[2 * q];
                f[2 * q] = t.x; f[2 * q + 1] = t.y;
            }
            #pragma unroll
            for (int dx = 0; dx < 9; ++dx) {
                accA[dx] = fmaf(fv.x, f[dx],     accA[dx]);
                accB[dx] = fmaf(fv.y, f[dx + 1], accB[dx]);
            }
        }
        __syncthreads();
    }

    if (IS_A) {
        float lsum = 0.f;
        #pragma unroll
        for (int dx = 0; dx < 9; ++dx) {
            int k = dy * 9 + dx;
            float m = g_m[k], w = g_w[k], lab = g_label[k];
            float cm = 0.5f * (1.0f - m), cp = 0.5f * (1.0f + m);

            float sA = accA[dx];
            float sgnA = (sA > 0.f) ? 1.0f : ((sA < 0.f) ? -1.0f : 0.0f);
            float sactA = cm * fabsf(sA) + cp * sA;
            float smaskA = cm * sgnA + cp;
            float lrA = w * (sactA - lab);

            float sB = accB[dx];
            float sgnB = (sB > 0.f) ? 1.0f : ((sB < 0.f) ? -1.0f : 0.0f);
            float sactB = cm * fabsf(sB) + cp * sB;
            float smaskB = cm * sgnB + cp;
            float lrB = w * (sactB - lab);

            size_t base = (((size_t)b * KK + k) << 10) + (y << 5) + x0;
            *(float2*)&g_mr[base] = make_float2(smaskA * w * lrA, smaskB * w * lrB);
            *(float2*)&g_wm[base] = make_float2(w * smaskA, w * smaskB);
            lsum += lrA * lrA + lrB * lrB;
        }
        s_red[tid] = lsum;
        __syncthreads();
        #pragma unroll
        for (int o = 32; o > 0; o >>= 1) {
            if (tid < o) s_red[tid] += s_red[tid + o];
            __syncthreads();
        }
        if (tid == 0) atomicAdd(&g_lr2[iter], s_red[0]);
    } else {
        float denA = 0.f, denB = 0.f;
        #pragma unroll
        for (int dx = 0; dx < 9; ++dx) {
            int k = dy * 9 + dx;
            size_t base = (((size_t)b * KK + k) << 10) + (y << 5) + x0;
            float2 wm2 = *(const float2*)&g_wm[base];
            float sgA = wm2.x * accA[dx];
            float sgB = wm2.y * accB[dx];
            denA += sgA * sgA;
            denB += sgB * sgB;
        }
        int p = (b << 10) + (y << 5) + x0;
        atomicAdd(&g_alpha_den[p], denA);
        atomicAdd(&g_alpha_den[p + 1], denB);
    }
}

// ---------------- transpose correlation: filter_grad, dy-split 2-pass, 2px/thread ----
// Grid: (4 ytiles, 16 channel-splits, 16 batch). Block: 128 = 8 rows x 16 pixel-pairs.
// Each thread owns 2 adjacent x pixels; float2 window rows -> 5 LDS.64 per 18 FMA.
// PASS=0: dy 0..4 (2x45 residual regs), writes partial g (float2) to g_fgrad.
// PASS=1: dy 5..8 (2x36 regs), adds partial + reg term, writes final g,
//         accumulates alpha_num and flt^2.
template <int PASS>
__global__ __launch_bounds__(128)
void k_btrans(const float* __restrict__ flt, const float* __restrict__ feat, int iter) {
    constexpr int DY0 = PASS ? 5 : 0;
    constexpr int NDY = PASS ? 4 : 5;
    constexpr int RB  = PASS ? 1 : -4;   // staged row base offset from y0

    __shared__ __align__(16) float s_feat[2][8][12][40];   // 30 KB
    __shared__ float s_red[128];

    const int tid = threadIdx.x;
    const int txq = tid & 15;         // 0..15
    const int ty = tid >> 4;          // 0..7
    const int b  = blockIdx.z;
    const int cs = blockIdx.y;        // 0..15 (16 channels each)
    const int y0 = blockIdx.x * 8;
    const int y  = y0 + ty;
    const int x0 = 2 * txq;

    const float rw = g_params[1];

    // pre-zero both buffers (halo rows/cols stay zero)
    {
        float* sf = &s_feat[0][0][0][0];
        for (int i = tid; i < 2 * 8 * 12 * 40; i += 128) sf[i] = 0.f;
    }

    float mrvA[NDY * 9], mrvB[NDY * 9];
    #pragma unroll
    for (int k = 0; k < NDY * 9; ++k) {
        float2 m2 = *(const float2*)&g_mr[(((size_t)b * KK + DY0 * 9 + k) << 10) + (y << 5) + x0];
        mrvA[k] = m2.x; mrvB[k] = m2.y;
    }

    __syncthreads();

    auto prefetch = [&](int cc, int buf) {
        const float* featb = feat + ((size_t)(b * CC + cs * 16 + cc * 8)) * NPIX;
        #pragma unroll
        for (int j = 0; j < 6; ++j) {
            int i = tid + j * 128;        // 0..767
            int c = i / 96; int rem = i % 96;
            int r = rem >> 3; int q = rem & 7;
            int grow = y0 + RB + r;
            if ((unsigned)grow < 32u) {
                uint32_t dst = smem_u32(&s_feat[buf][c][r][4 + q * 4]);
                CP_ASYNC16(dst, featb + c * NPIX + grow * WW + q * 4);
            }
        }
        CP_COMMIT();
    };

    float anumA = 0.f, anumB = 0.f, fl2 = 0.f;

    prefetch(0, 0);

    for (int cc = 0; cc < 2; ++cc) {
        const int buf = cc & 1;
        if (cc < 1) { prefetch(cc + 1, buf ^ 1); cp_wait<1>(); }
        else        { cp_wait<0>(); }
        __syncthreads();

        const int cbase = cs * 16 + cc * 8;
        #pragma unroll
        for (int c = 0; c < 8; ++c) {
            float gA = 0.f, gB = 0.f;
            #pragma unroll
            for (int ldy = 0; ldy < NDY; ++ldy) {
                const float* fr = &s_feat[buf][c][ty + ldy][x0];
                float f[10];
                #pragma unroll
                for (int q = 0; q < 5; ++q) {
                    float2 t = *(const float2*)&fr[2 * q];
                    f[2 * q] = t.x; f[2 * q + 1] = t.y;
                }
                #pragma unroll
                for (int dx = 0; dx < 9; ++dx) {
                    gA = fmaf(mrvA[ldy * 9 + dx], f[dx],     gA);
                    gB = fmaf(mrvB[ldy * 9 + dx], f[dx + 1], gB);
                }
            }
            size_t gidx = (((size_t)(b * CC + cbase + c)) << 10) + (y << 5) + x0;
            if (PASS == 0) {
                *(float2*)&g_fgrad[gidx] = make_float2(gA, gB);
            } else {
                float2 part = *(const float2*)&g_fgrad[gidx];
                float2 flv  = *(const float2*)&flt[gidx];
                gA += part.x; gB += part.y;
                gA = fmaf(rw, flv.x, gA);
                gB = fmaf(rw, flv.y, gB);
                *(float2*)&g_fgrad[gidx] = make_float2(gA, gB);
                anumA += gA * gA;
                anumB += gB * gB;
                fl2 += flv.x * flv.x + flv.y * flv.y;
            }
        }
        __syncthreads();
    }

    if (PASS == 1) {
        int p = (b << 10) + (y << 5) + x0;
        atomicAdd(&g_alpha_num[p], anumA);
        atomicAdd(&g_alpha_num[p + 1], anumB);
        s_red[tid] = fl2;
        __syncthreads();
        #pragma unroll
        for (int o = 64; o > 0; o >>= 1) {
            if (tid < o) s_red[tid] += s_red[tid + o];
            __syncthreads();
        }
        if (tid == 0) atomicAdd(&g_flt2[iter], s_red[0]);
    }
}

// ---------------- filter update: out = src - step*alpha*grad ----------------
__global__ void k_update(float* __restrict__ dst, const float* __restrict__ src) {
    int idx = blockIdx.x * 256 + threadIdx.x;
    float step = g_params[0], rw = g_params[1];
    int spix = idx & 1023;
    int b = idx >> 18;                 // / (256*1024)
    int p = (b << 10) + spix;
    float num = g_alpha_num[p];
    float den = g_alpha_den[p] + rw * num;
    den = fmaxf(den, 1e-8f);
    float alpha = num / den;
    dst[idx] = src[idx] - step * alpha * g_fgrad[idx];
}

// ---------------- final scalars ----------------
__global__ void k_fin(float* __restrict__ out) {
    int i = threadIdx.x;
    if (i < 3) {
        float rw = g_params[1];
        float src = 0.5f * g_lr2[i] / (float)BB;
        float reg = 0.5f * rw * g_flt2[i] / (float)BB;
        out[FLT_ELEMS + i]     = src + reg;   // tr
        out[FLT_ELEMS + 3 + i] = src;         // tr_src
        out[FLT_ELEMS + 6 + i] = reg;         // tr_reg
    }
}

// ---------------- launch ----------------
extern "C" void kernel_launch(void* const* d_in, const int* in_sizes, int n_in,
                              void* d_out, int out_size) {
    const float* flt_in = (const float*)d_in[0];
    const float* feat   = (const float*)d_in[1];
    const float* lw     = (const float*)d_in[2];
    const float* mw     = (const float*)d_in[3];
    const float* sw     = (const float*)d_in[4];
    const float* lsl    = (const float*)d_in[5];
    const float* fr     = (const float*)d_in[6];
    float* out = (float*)d_out;

    k_pre<<<1, 128>>>(lw, mw, sw, lsl, fr);

    for (int it = 0; it < 3; ++it) {
        const float* fsrc = (it == 0) ? flt_in : out;
        k_zero<<<64, 256>>>();
        k_corrF<true><<<dim3(72, 1, BB), 64>>>(fsrc, feat, it);
        k_btrans<0><<<dim3(4, 16, BB), 128>>>(fsrc, feat, it);
        k_btrans<1><<<dim3(4, 16, BB), 128>>>(fsrc, feat, it);
        k_corrF<false><<<dim3(72, 1, BB), 64>>>(nullptr, feat, it);
        k_update<<<FLT_ELEMS / 256, 256>>>(out, fsrc);
    }

    if (out_size >= FLT_ELEMS + 9)
        k_fin<<<1, 32>>>(out);
}